// round 15
// baseline (speedup 1.0000x reference)
#include <cuda_runtime.h>
#include <cuda_bf16.h>
#include <math.h>
#include <stdint.h>

// Problem constants
#define BB   4
#define TT   2048
#define DM   1024
#define HH   16
#define HD   64
#define NF   128
#define CC   128
#define NCH  (TT/CC)          // 16
#define ROWS (BB*TT)          // 8192
#define BHT  (BB*HH*TT)       // 131072
#define EPSV 1e-6f
#define INV_SQRT_NF 0.08838834764831845f

// ---------------- scratch (device globals) ------------------------------------
__device__ float g_q [ROWS*DM];
__device__ float g_k [ROWS*DM];
__device__ float g_S [(size_t)BB*HH*NCH*NF*HD];
__device__ float g_z [(size_t)BB*HH*NCH*NF];
__device__ __nv_bfloat16 g_xh[ROWS*DM];
__device__ __nv_bfloat16 g_xl[ROWS*DM];
__device__ __nv_bfloat16 g_vh[ROWS*DM];
__device__ __nv_bfloat16 g_vl[ROWS*DM];
__device__ __nv_bfloat16 g_yh[ROWS*DM];
__device__ __nv_bfloat16 g_yl[ROWS*DM];
__device__ __nv_bfloat16 g_qph[(size_t)BHT*NF];
__device__ __nv_bfloat16 g_qpl[(size_t)BHT*NF];
__device__ __nv_bfloat16 g_kph[(size_t)BHT*NF];
__device__ __nv_bfloat16 g_kpl[(size_t)BHT*NF];
__device__ __nv_bfloat16 g_wh[4*DM*DM];   // transposed weights hi [4096,1024]
__device__ __nv_bfloat16 g_wl[4*DM*DM];   // transposed weights lo

// ======================= PTX helpers ==========================================
__device__ __forceinline__ uint32_t smem_u32(const void* p) {
    uint32_t a;
    asm("{ .reg .u64 t; cvta.to.shared.u64 t, %1; cvt.u32.u64 %0, t; }"
        : "=r"(a) : "l"(p));
    return a;
}
__device__ __forceinline__ void cp16(uint32_t d, const void* g) {
    asm volatile("cp.async.cg.shared.global [%0], [%1], 16;" :: "r"(d), "l"(g));
}
__device__ __forceinline__ void ldm_x4(uint32_t* r, uint32_t a) {
    asm volatile("ldmatrix.sync.aligned.m8n8.x4.shared.b16 {%0,%1,%2,%3}, [%4];"
                 : "=r"(r[0]), "=r"(r[1]), "=r"(r[2]), "=r"(r[3]) : "r"(a));
}
__device__ __forceinline__ void ldm_x4t(uint32_t* r, uint32_t a) {
    asm volatile("ldmatrix.sync.aligned.m8n8.x4.trans.shared.b16 {%0,%1,%2,%3}, [%4];"
                 : "=r"(r[0]), "=r"(r[1]), "=r"(r[2]), "=r"(r[3]) : "r"(a));
}
__device__ __forceinline__ void mma16816(float* c, const uint32_t* a, const uint32_t* b) {
    asm volatile(
        "mma.sync.aligned.m16n8k16.row.col.f32.bf16.bf16.f32 "
        "{%0,%1,%2,%3}, {%4,%5,%6,%7}, {%8,%9}, {%0,%1,%2,%3};"
        : "+f"(c[0]), "+f"(c[1]), "+f"(c[2]), "+f"(c[3])
        : "r"(a[0]), "r"(a[1]), "r"(a[2]), "r"(a[3]), "r"(b[0]), "r"(b[1]));
}
__device__ __forceinline__ __nv_bfloat162 split_pair(float a, float b,
                                                     __nv_bfloat162& lo) {
    __nv_bfloat16 h0 = __float2bfloat16(a);
    __nv_bfloat16 h1 = __float2bfloat16(b);
    __nv_bfloat16 l0 = __float2bfloat16(a - __bfloat162float(h0));
    __nv_bfloat16 l1 = __float2bfloat16(b - __bfloat162float(h1));
    lo.x = l0; lo.y = l1;
    __nv_bfloat162 hi; hi.x = h0; hi.y = h1;
    return hi;
}

// ======================= bf16 split / transpose ===============================
__global__ __launch_bounds__(256) void split_kernel(const float* __restrict__ x,
                                                    __nv_bfloat16* __restrict__ h,
                                                    __nv_bfloat16* __restrict__ l,
                                                    int n4) {
    int i = blockIdx.x * blockDim.x + threadIdx.x;
    int stride = gridDim.x * blockDim.x;
    for (; i < n4; i += stride) {
        float4 v = ((const float4*)x)[i];
        __nv_bfloat162 la, lb;
        __nv_bfloat162 ha = split_pair(v.x, v.y, la);
        __nv_bfloat162 hb = split_pair(v.z, v.w, lb);
        ((__nv_bfloat162*)h)[2 * i]     = ha;
        ((__nv_bfloat162*)h)[2 * i + 1] = hb;
        ((__nv_bfloat162*)l)[2 * i]     = la;
        ((__nv_bfloat162*)l)[2 * i + 1] = lb;
    }
}

// All four weights in one launch, blockIdx.z selects matrix.
__global__ __launch_bounds__(256) void wsplit4_kernel(
    const float* __restrict__ W0, const float* __restrict__ W1,
    const float* __restrict__ W2, const float* __restrict__ W3,
    __nv_bfloat16* __restrict__ th, __nv_bfloat16* __restrict__ tl) {
    __shared__ float t[32][33];
    int z = blockIdx.z;
    const float* W = (z == 0) ? W0 : (z == 1) ? W1 : (z == 2) ? W2 : W3;
    th += (size_t)z * DM * DM;
    tl += (size_t)z * DM * DM;
    int bn = blockIdx.x * 32, bk = blockIdx.y * 32;
    int tx = threadIdx.x & 31, ty = threadIdx.x >> 5;
    for (int r = ty; r < 32; r += 8)
        t[r][tx] = W[(size_t)(bk + r) * DM + bn + tx];
    __syncthreads();
    for (int r = ty; r < 32; r += 8) {
        float v = t[tx][r];
        __nv_bfloat16 h = __float2bfloat16(v);
        __nv_bfloat16 l = __float2bfloat16(v - __bfloat162float(h));
        th[(size_t)(bn + r) * DM + bk + tx] = h;
        tl[(size_t)(bn + r) * DM + bk + tx] = l;
    }
}

// ======================= big-tile mma.sync bf16x3 GEMM ========================
// Block tile 128x256x32, 16 warps (4M x 4N), warp tile 32x64, 3 stages.
#define BGM 128
#define BGN 256
#define BGK 32
#define BNK (DM / BGK)            // 32
#define BROWB 80
#define BSA_H 0
#define BSA_L (128 * BROWB)       // 10240
#define BSB_H (2 * 128 * BROWB)   // 20480
#define BSB_L (BSB_H + 256 * BROWB)
#define BSTAGE_B (BSB_L + 256 * BROWB)   // 61440
#define BSMEM (3 * BSTAGE_B)             // 184320

__device__ __forceinline__ void bload_stage(uint32_t sbase, int tid,
                                            const __nv_bfloat16* ah,
                                            const __nv_bfloat16* al,
                                            const __nv_bfloat16* bh,
                                            const __nv_bfloat16* bl, int k0) {
    int r0 = tid >> 2, ch = tid & 3;   // r0 0..127
    cp16(sbase + BSA_H + r0 * BROWB + ch * 16, ah + (size_t)r0 * DM + k0 + ch * 8);
    cp16(sbase + BSA_L + r0 * BROWB + ch * 16, al + (size_t)r0 * DM + k0 + ch * 8);
#pragma unroll
    for (int j = 0; j < 4; j++) {
        const __nv_bfloat16* base = (j < 2) ? bh : bl;
        int r = (j & 1) * 128 + r0;
        cp16(sbase + ((j < 2) ? BSB_H : BSB_L) + r * BROWB + ch * 16,
             base + (size_t)r * DM + k0 + ch * 8);
    }
}

// MODE 0: all columns fp32 -> Cq.   MODE 1: QKV mixed (q,k fp32; v bf16 h/l).
template <int MODE>
__global__ __launch_bounds__(512, 1) void gemm_big(
    const __nv_bfloat16* __restrict__ Ah, const __nv_bfloat16* __restrict__ Al,
    const __nv_bfloat16* __restrict__ Bh, const __nv_bfloat16* __restrict__ Bl,
    float* __restrict__ Cq, float* __restrict__ Ck,
    __nv_bfloat16* __restrict__ Cvh, __nv_bfloat16* __restrict__ Cvl) {
    extern __shared__ char smem[];
    uint32_t sm = smem_u32(smem);
    int tid = threadIdx.x, lane = tid & 31, wid = tid >> 5;
    int wm = wid & 3, wn = wid >> 2;   // 4x4 warps, warp tile 32x64
    int bm = blockIdx.y * BGM, bn = blockIdx.x * BGN;

    const __nv_bfloat16* pAh = Ah + (size_t)bm * DM;
    const __nv_bfloat16* pAl = Al + (size_t)bm * DM;
    const __nv_bfloat16* pBh = Bh + (size_t)bn * DM;
    const __nv_bfloat16* pBl = Bl + (size_t)bn * DM;

    float acc[2][8][4];
#pragma unroll
    for (int mt = 0; mt < 2; mt++)
#pragma unroll
        for (int nt = 0; nt < 8; nt++)
#pragma unroll
            for (int i = 0; i < 4; i++) acc[mt][nt][i] = 0.f;

#pragma unroll
    for (int s = 0; s < 2; s++) {
        bload_stage(sm + s * BSTAGE_B, tid, pAh, pAl, pBh, pBl, s * BGK);
        asm volatile("cp.async.commit_group;");
    }

    int a_row = lane & 15;
    int a_koff = (lane >= 16) ? 8 : 0;
    int b_row = (lane & 7) + ((lane >> 4) << 3);
    int b_koff = ((lane >> 3) & 1) * 8;

    for (int kt = 0; kt < BNK; kt++) {
        asm volatile("cp.async.wait_group 1;");
        __syncthreads();
        int pf = kt + 2;
        if (pf < BNK)
            bload_stage(sm + (pf % 3) * BSTAGE_B, tid, pAh, pAl, pBh, pBl,
                        pf * BGK);
        asm volatile("cp.async.commit_group;");

        uint32_t sb = sm + (kt % 3) * BSTAGE_B;
#pragma unroll
        for (int k16 = 0; k16 < 2; k16++) {
            uint32_t fah[2][4], fal[2][4];
#pragma unroll
            for (int mt = 0; mt < 2; mt++) {
                uint32_t addr = sb + BSA_H + (wm * 32 + mt * 16 + a_row) * BROWB +
                                (k16 * 16 + a_koff) * 2;
                ldm_x4(fah[mt], addr);
                ldm_x4(fal[mt], addr + (BSA_L - BSA_H));
            }
#pragma unroll
            for (int half = 0; half < 2; half++) {
                uint32_t fbh[4][2], fbl[4][2];
#pragma unroll
                for (int ntp = 0; ntp < 2; ntp++) {
                    uint32_t addr = sb + BSB_H +
                                    (wn * 64 + half * 32 + ntp * 16 + b_row) * BROWB +
                                    (k16 * 16 + b_koff) * 2;
                    uint32_t t4[4];
                    ldm_x4(t4, addr);
                    fbh[2 * ntp][0] = t4[0]; fbh[2 * ntp][1] = t4[1];
                    fbh[2 * ntp + 1][0] = t4[2]; fbh[2 * ntp + 1][1] = t4[3];
                    ldm_x4(t4, addr + (BSB_L - BSB_H));
                    fbl[2 * ntp][0] = t4[0]; fbl[2 * ntp][1] = t4[1];
                    fbl[2 * ntp + 1][0] = t4[2]; fbl[2 * ntp + 1][1] = t4[3];
                }
#pragma unroll
                for (int mt = 0; mt < 2; mt++)
#pragma unroll
                    for (int n4 = 0; n4 < 4; n4++) {
                        float* a4 = acc[mt][half * 4 + n4];
                        mma16816(a4, fah[mt], fbh[n4]);
                        mma16816(a4, fal[mt], fbh[n4]);
                        mma16816(a4, fah[mt], fbl[n4]);
                    }
            }
        }
    }

    int gid = lane >> 2, tig = lane & 3;
#pragma unroll
    for (int mt = 0; mt < 2; mt++) {
#pragma unroll
        for (int nt = 0; nt < 8; nt++) {
#pragma unroll
            for (int rh = 0; rh < 2; rh++) {
                int row = bm + wm * 32 + mt * 16 + gid + rh * 8;
                int colg = bn + wn * 64 + nt * 8 + tig * 2;
                float c0 = acc[mt][nt][2 * rh], c1 = acc[mt][nt][2 * rh + 1];
                if (MODE == 0) {
                    *(float2*)(Cq + (size_t)row * DM + colg) = make_float2(c0, c1);
                } else {
                    int region = colg >> 10, cl = colg & 1023;
                    if (region == 0) {
                        *(float2*)(Cq + (size_t)row * DM + cl) = make_float2(c0, c1);
                    } else if (region == 1) {
                        *(float2*)(Ck + (size_t)row * DM + cl) = make_float2(c0, c1);
                    } else {
                        __nv_bfloat162 lo;
                        __nv_bfloat162 hi = split_pair(c0, c1, lo);
                        *(__nv_bfloat162*)(Cvh + (size_t)row * DM + cl) = hi;
                        *(__nv_bfloat162*)(Cvl + (size_t)row * DM + cl) = lo;
                    }
                }
            }
        }
    }
}

// ---------------- FAVOR+ feature map via MMA (2 CTAs/SM, q+k fused) ----------
// smem: qh/ql 128x144B, wh/wl 128x144B, sq 128 floats  => 74240 B
#define F2QH 0
#define F2QL (F2QH + 18432)
#define F2WH (F2QL + 18432)
#define F2WL (F2WH + 18432)
#define F2SQ (F2WL + 18432)
#define F2SMEM (F2SQ + 512)

__global__ __launch_bounds__(256, 2) void feature_mma_kernel(
    const float* __restrict__ q, const float* __restrict__ k,
    const float* __restrict__ Wf,
    __nv_bfloat16* __restrict__ qph, __nv_bfloat16* __restrict__ qpl,
    __nv_bfloat16* __restrict__ kph, __nv_bfloat16* __restrict__ kpl) {
    extern __shared__ char smem[];
    uint32_t sm = smem_u32(smem);
    int tid = threadIdx.x, lane = tid & 31, wid = tid >> 5;
    int row0 = blockIdx.x * 128;
    int bh = row0 / TT, t0 = row0 % TT;
    int b = bh >> 4, h = bh & 15;

    // W_feat split + transpose -> [f][d], once per block
    for (int i = tid; i < 8192; i += 256) {
        int d = i >> 7, f = i & 127;
        float v = Wf[i];
        __nv_bfloat16 h16 = __float2bfloat16(v);
        __nv_bfloat16 l16 = __float2bfloat16(v - __bfloat162float(h16));
        ((__nv_bfloat16*)(smem + F2WH))[f * 72 + d] = h16;
        ((__nv_bfloat16*)(smem + F2WL))[f * 72 + d] = l16;
    }

    float* sqf = (float*)(smem + F2SQ);
    int wm = wid & 3, wn = wid >> 2;
    int gid = lane >> 2, tig = lane & 3;
    int a_row = lane & 15, a_koff = (lane >= 16) ? 8 : 0;
    int b_row = (lane & 7) + ((lane >> 4) << 3);
    int b_koff = ((lane >> 3) & 1) * 8;

    for (int p = 0; p < 2; p++) {
        const float* src = p ? k : q;
        __nv_bfloat16* dh = p ? kph : qph;
        __nv_bfloat16* dl = p ? kpl : qpl;
        const float* base = src + ((size_t)(b * TT + t0)) * DM + h * HD;

        __syncthreads();                 // prev pass fully done / Wf ready
        if (tid < 128) sqf[tid] = 0.f;
        __syncthreads();

        // load fp32, split to bf16 h/l in smem, accumulate ||q||^2 via atomics
        for (int i = tid; i < 4096; i += 256) {
            int r = i >> 5, c2 = i & 31;
            float2 v = *(const float2*)(base + (size_t)r * DM + c2 * 2);
            __nv_bfloat162 lo;
            __nv_bfloat162 hi = split_pair(v.x, v.y, lo);
            *(__nv_bfloat162*)(smem + F2QH + r * 144 + c2 * 4) = hi;
            *(__nv_bfloat162*)(smem + F2QL + r * 144 + c2 * 4) = lo;
            atomicAdd(sqf + r, v.x * v.x + v.y * v.y);
        }
        __syncthreads();

        // per n-half: MMA 32rows x 32f x K=64, then epilogue for that half
#pragma unroll
        for (int nh = 0; nh < 2; nh++) {
            float acc[2][4][4];
#pragma unroll
            for (int mt = 0; mt < 2; mt++)
#pragma unroll
                for (int nt = 0; nt < 4; nt++)
#pragma unroll
                    for (int i = 0; i < 4; i++) acc[mt][nt][i] = 0.f;

#pragma unroll
            for (int kt = 0; kt < 4; kt++) {
                uint32_t fah[2][4], fal[2][4];
#pragma unroll
                for (int mt = 0; mt < 2; mt++) {
                    uint32_t addr = sm + F2QH + (wm * 32 + mt * 16 + a_row) * 144 +
                                    (kt * 16 + a_koff) * 2;
                    ldm_x4(fah[mt], addr);
                    ldm_x4(fal[mt], addr + (F2QL - F2QH));
                }
                uint32_t fbh[4][2], fbl[4][2];
#pragma unroll
                for (int ntp = 0; ntp < 2; ntp++) {
                    uint32_t addr = sm + F2WH +
                                    (wn * 64 + nh * 32 + ntp * 16 + b_row) * 144 +
                                    (kt * 16 + b_koff) * 2;
                    uint32_t t4[4];
                    ldm_x4(t4, addr);
                    fbh[2 * ntp][0] = t4[0]; fbh[2 * ntp][1] = t4[1];
                    fbh[2 * ntp + 1][0] = t4[2]; fbh[2 * ntp + 1][1] = t4[3];
                    ldm_x4(t4, addr + (F2WL - F2WH));
                    fbl[2 * ntp][0] = t4[0]; fbl[2 * ntp][1] = t4[1];
                    fbl[2 * ntp + 1][0] = t4[2]; fbl[2 * ntp + 1][1] = t4[3];
                }
#pragma unroll
                for (int mt = 0; mt < 2; mt++)
#pragma unroll
                    for (int nt = 0; nt < 4; nt++) {
                        mma16816(acc[mt][nt], fah[mt], fbh[nt]);
                        mma16816(acc[mt][nt], fal[mt], fbh[nt]);
                        mma16816(acc[mt][nt], fah[mt], fbl[nt]);
                    }
            }

#pragma unroll
            for (int mt = 0; mt < 2; mt++)
#pragma unroll
                for (int nt = 0; nt < 4; nt++)
#pragma unroll
                    for (int rh = 0; rh < 2; rh++) {
                        int row = wm * 32 + mt * 16 + gid + rh * 8;
                        int f = wn * 64 + nh * 32 + nt * 8 + tig * 2;
                        float s = 0.5f * sqf[row];
                        float v0 = expf(acc[mt][nt][2 * rh] - s) * INV_SQRT_NF;
                        float v1 = expf(acc[mt][nt][2 * rh + 1] - s) * INV_SQRT_NF;
                        __nv_bfloat162 lo;
                        __nv_bfloat162 hi = split_pair(v0, v1, lo);
                        size_t o = (size_t)(row0 + row) * NF + f;
                        *(__nv_bfloat162*)(dh + o) = hi;
                        *(__nv_bfloat162*)(dl + o) = lo;
                    }
        }
    }
}

// ---------------- per-chunk K^T V via MMA -------------------------------------
#define CKH 0
#define CKL 34816
#define CVH 69632
#define CVL (CVH + 18432)
#define CZP (CVL + 18432)
#define CSMEM (CZP + 1024)

__global__ __launch_bounds__(256, 1) void chunk_kv_mma(
    const __nv_bfloat16* __restrict__ kph, const __nv_bfloat16* __restrict__ kpl,
    const __nv_bfloat16* __restrict__ vh, const __nv_bfloat16* __restrict__ vl,
    float* __restrict__ Sc, float* __restrict__ zc) {
    int blk = blockIdx.x;
    int c = blk % NCH, bh = blk / NCH;
    int b = bh / HH, h = bh % HH;

    extern __shared__ char smem[];
    uint32_t sm = smem_u32(smem);
    int tid = threadIdx.x, lane = tid & 31, wid = tid >> 5;

    size_t gbase = ((size_t)bh * TT + c * CC) * NF;
    for (int i = tid; i < 2048; i += 256) {
        int r = i >> 4, c8 = i & 15;
        *(uint4*)(smem + CKH + r * 272 + c8 * 16) = ((const uint4*)(kph + gbase))[i];
        *(uint4*)(smem + CKL + r * 272 + c8 * 16) = ((const uint4*)(kpl + gbase))[i];
    }
    for (int i = tid; i < 1024; i += 256) {
        int r = i >> 3, c8 = i & 7;
        size_t go = (size_t)(b * TT + c * CC + r) * DM + h * HD + c8 * 8;
        *(uint4*)(smem + CVH + r * 144 + c8 * 16) = *(const uint4*)(vh + go);
        *(uint4*)(smem + CVL + r * 144 + c8 * 16) = *(const uint4*)(vl + go);
    }
    __syncthreads();

    {
        int f = tid & 127, half = tid >> 7;
        float s = 0.f;
        const __nv_bfloat16* kh_ = (const __nv_bfloat16*)(smem + CKH);
        const __nv_bfloat16* kl_ = (const __nv_bfloat16*)(smem + CKL);
        for (int t = half * 64; t < half * 64 + 64; t++)
            s += __bfloat162float(kh_[t * 136 + f]) + __bfloat162float(kl_[t * 136 + f]);
        ((float*)(smem + CZP))[half * 128 + f] = s;
    }

    int wm = wid & 3, wn = (wid >> 2) & 1;
    int f0 = wm * 32, e0 = wn * 32;
    int r7 = lane & 7, oct = lane >> 3;
    int krow = r7 + ((oct >> 1) & 1) * 8;
    int mcol = (oct & 1) * 8;
    int bt_row = (lane & 7) + ((lane >> 3) & 1) * 8;
    int bt_nt = lane >> 4;

    float acc[2][4][4];
#pragma unroll
    for (int mt = 0; mt < 2; mt++)
#pragma unroll
        for (int nt = 0; nt < 4; nt++)
#pragma unroll
            for (int i = 0; i < 4; i++) acc[mt][nt][i] = 0.f;

#pragma unroll
    for (int kt = 0; kt < 8; kt++) {
        int t0 = kt * 16;
        uint32_t fah[2][4], fal[2][4];
#pragma unroll
        for (int mt = 0; mt < 2; mt++) {
            uint32_t addr = sm + CKH + (t0 + krow) * 272 + (f0 + mt * 16 + mcol) * 2;
            ldm_x4t(fah[mt], addr);
            ldm_x4t(fal[mt], addr + (CKL - CKH));
        }
        uint32_t fbh[4][2], fbl[4][2];
#pragma unroll
        for (int ntp = 0; ntp < 2; ntp++) {
            uint32_t addr = sm + CVH + (t0 + bt_row) * 144 +
                            (e0 + ntp * 16 + bt_nt * 8) * 2;
            uint32_t t4[4];
            ldm_x4t(t4, addr);
            fbh[2 * ntp][0] = t4[0]; fbh[2 * ntp][1] = t4[1];
            fbh[2 * ntp + 1][0] = t4[2]; fbh[2 * ntp + 1][1] = t4[3];
            ldm_x4t(t4, addr + (CVL - CVH));
            fbl[2 * ntp][0] = t4[0]; fbl[2 * ntp][1] = t4[1];
            fbl[2 * ntp + 1][0] = t4[2]; fbl[2 * ntp + 1][1] = t4[3];
        }
#pragma unroll
        for (int mt = 0; mt < 2; mt++)
#pragma unroll
            for (int nt = 0; nt < 4; nt++) {
                mma16816(acc[mt][nt], fah[mt], fbh[nt]);
                mma16816(acc[mt][nt], fal[mt], fbh[nt]);
                mma16816(acc[mt][nt], fah[mt], fbl[nt]);
            }
    }

    __syncthreads();
    if (tid < 128) {
        const float* zp_ = (const float*)(smem + CZP);
        zc[(size_t)blk * NF + tid] = zp_[tid] + zp_[128 + tid];
    }

    int gid = lane >> 2, tig = lane & 3;
    float* Sbase = Sc + (size_t)blk * NF * HD;
#pragma unroll
    for (int mt = 0; mt < 2; mt++)
#pragma unroll
        for (int nt = 0; nt < 4; nt++)
#pragma unroll
            for (int rh = 0; rh < 2; rh++) {
                int f = f0 + mt * 16 + gid + rh * 8;
                int e = e0 + nt * 8 + tig * 2;
                *(float2*)(Sbase + (size_t)f * HD + e) =
                    make_float2(acc[mt][nt][2 * rh], acc[mt][nt][2 * rh + 1]);
            }
}

// ---------------- exclusive prefix over chunks --------------------------------
__global__ __launch_bounds__(256) void prefix_kernel(float* __restrict__ Sc,
                                                     float* __restrict__ zc) {
    int bh = blockIdx.x;
    int quarter = blockIdx.y;
    int tid = threadIdx.x;
    int lo = quarter * (NF * HD / 4), hi = lo + (NF * HD / 4);
    for (int idx = lo + tid; idx < hi; idx += 256) {
        float run = 0.f;
        float* p = Sc + (size_t)bh * NCH * NF * HD + idx;
        for (int c = 0; c < NCH; c++) {
            float t = p[(size_t)c * NF * HD];
            p[(size_t)c * NF * HD] = run;
            run += t;
        }
    }
    if (quarter == 0) {
        for (int idx = tid; idx < NF; idx += 256) {
            float run = 0.f;
            float* p = zc + (size_t)bh * NCH * NF + idx;
            for (int c = 0; c < NCH; c++) {
                float t = p[c * NF];
                p[c * NF] = run;
                run += t;
            }
        }
    }
}

// ---------------- MMA attention chunk kernel ----------------------------------
#define PQE 136
#define PQB (PQE * 2)
#define PVE 72
#define PVB (PVE * 2)
#define OQH 0
#define OQL (OQH + 128 * PQB)
#define OKH (OQL + 128 * PQB)
#define OKL (OKH + 128 * PQB)
#define OVH (OKL + 128 * PQB)
#define OVL (OVH + 128 * PVB)
#define OSH (OVL + 128 * PVB)
#define OSL (OSH + 128 * PVB)
#define ODEN (OSL + 128 * PVB)
#define OZ  (ODEN + 512)
#define ATTN_SMEM (OZ + 512)

__global__ __launch_bounds__(256, 1) void attn_mma_kernel(
    const __nv_bfloat16* __restrict__ qph, const __nv_bfloat16* __restrict__ qpl,
    const __nv_bfloat16* __restrict__ kph, const __nv_bfloat16* __restrict__ kpl,
    const __nv_bfloat16* __restrict__ vh, const __nv_bfloat16* __restrict__ vl,
    const float* __restrict__ Sp, const float* __restrict__ zp,
    __nv_bfloat16* __restrict__ yh, __nv_bfloat16* __restrict__ yl) {
    int blk = blockIdx.x;
    int c = blk % NCH, bh = blk / NCH;
    int b = bh / HH, h = bh % HH;

    extern __shared__ char smem[];
    uint32_t sm = smem_u32(smem);
    int tid = threadIdx.x, lane = tid & 31, wid = tid >> 5;

    {
        size_t base = ((size_t)bh * TT + c * CC) * NF;
        const uint4* sqh = (const uint4*)(qph + base);
        const uint4* sql = (const uint4*)(qpl + base);
        const uint4* skh = (const uint4*)(kph + base);
        const uint4* skl = (const uint4*)(kpl + base);
        for (int i = tid; i < 2048; i += 256) {
            int row = i >> 4, c8 = i & 15;
            int off = row * PQB + c8 * 16;
            *(uint4*)(smem + OQH + off) = sqh[i];
            *(uint4*)(smem + OQL + off) = sql[i];
            *(uint4*)(smem + OKH + off) = skh[i];
            *(uint4*)(smem + OKL + off) = skl[i];
        }
        for (int i = tid; i < 1024; i += 256) {
            int row = i >> 3, c8 = i & 7;
            size_t go = (size_t)(b * TT + c * CC + row) * DM + h * HD + c8 * 8;
            *(uint4*)(smem + OVH + row * PVB + c8 * 16) = *(const uint4*)(vh + go);
            *(uint4*)(smem + OVL + row * PVB + c8 * 16) = *(const uint4*)(vl + go);
        }
        const float4* sS = (const float4*)(Sp + (size_t)blk * NF * HD);
        for (int i = tid; i < 2048; i += 256) {
            int row = i >> 4, c4 = i & 15;
            float4 v = sS[i];
            __nv_bfloat162 l0, l1;
            __nv_bfloat162 h0 = split_pair(v.x, v.y, l0);
            __nv_bfloat162 h1 = split_pair(v.z, v.w, l1);
            uint2 hv, lv;
            hv.x = *(uint32_t*)&h0; hv.y = *(uint32_t*)&h1;
            lv.x = *(uint32_t*)&l0; lv.y = *(uint32_t*)&l1;
            *(uint2*)(smem + OSH + row * PVB + c4 * 8) = hv;
            *(uint2*)(smem + OSL + row * PVB + c4 * 8) = lv;
        }
        const float4* sz = (const float4*)(zp + (size_t)blk * NF);
        for (int i = tid; i < 32; i += 256)
            ((float4*)(smem + OZ))[i] = sz[i];
    }
    __syncthreads();

    int wm = wid & 3, wn = wid >> 2;
    int gid = lane >> 2, tig = lane & 3;
    int a_row = lane & 15, a_koff = (lane >= 16) ? 8 : 0;
    int b_row = (lane & 7) + ((lane >> 4) << 3);
    int b_koff = ((lane >> 3) & 1) * 8;

    float accA[2][8][4];
#pragma unroll
    for (int mt = 0; mt < 2; mt++)
#pragma unroll
        for (int nt = 0; nt < 8; nt++)
#pragma unroll
            for (int i = 0; i < 4; i++) accA[mt][nt][i] = 0.f;

#pragma unroll
    for (int kt = 0; kt < 8; kt++) {
        uint32_t fah[2][4], fal[2][4];
#pragma unroll
        for (int mt = 0; mt < 2; mt++) {
            uint32_t addr = sm + OQH + (wm * 32 + mt * 16 + a_row) * PQB +
                            (kt * 16 + a_koff) * 2;
            ldm_x4(fah[mt], addr);
            ldm_x4(fal[mt], addr + (OQL - OQH));
        }
        uint32_t fbh[8][2], fbl[8][2];
#pragma unroll
        for (int ntp = 0; ntp < 4; ntp++) {
            uint32_t addr = sm + OKH + (wn * 64 + ntp * 16 + b_row) * PQB +
                            (kt * 16 + b_koff) * 2;
            uint32_t t4[4];
            ldm_x4(t4, addr);
            fbh[2 * ntp][0] = t4[0]; fbh[2 * ntp][1] = t4[1];
            fbh[2 * ntp + 1][0] = t4[2]; fbh[2 * ntp + 1][1] = t4[3];
            ldm_x4(t4, addr + (OKL - OKH));
            fbl[2 * ntp][0] = t4[0]; fbl[2 * ntp][1] = t4[1];
            fbl[2 * ntp + 1][0] = t4[2]; fbl[2 * ntp + 1][1] = t4[3];
        }
#pragma unroll
        for (int mt = 0; mt < 2; mt++)
#pragma unroll
            for (int nt = 0; nt < 8; nt++) {
                mma16816(accA[mt][nt], fah[mt], fbh[nt]);
                mma16816(accA[mt][nt], fal[mt], fbh[nt]);
                mma16816(accA[mt][nt], fah[mt], fbl[nt]);
            }
    }
    __syncthreads();

#pragma unroll
    for (int mt = 0; mt < 2; mt++)
#pragma unroll
        for (int nt = 0; nt < 8; nt++)
#pragma unroll
            for (int rh = 0; rh < 2; rh++) {
                int row = wm * 32 + mt * 16 + gid + rh * 8;
                int col = wn * 64 + nt * 8 + tig * 2;
                float c0 = accA[mt][nt][2 * rh], c1 = accA[mt][nt][2 * rh + 1];
                if (col > row) c0 = 0.f;
                if (col + 1 > row) c1 = 0.f;
                __nv_bfloat162 lo;
                __nv_bfloat162 hi = split_pair(c0, c1, lo);
                *(__nv_bfloat162*)(smem + OKH + row * PQB + col * 2) = hi;
                *(__nv_bfloat162*)(smem + OKL + row * PQB + col * 2) = lo;
            }
    __syncthreads();

    if (tid < 128) {
        const __nv_bfloat16* ah_ = (const __nv_bfloat16*)(smem + OKH + tid * PQB);
        const __nv_bfloat16* al_ = (const __nv_bfloat16*)(smem + OKL + tid * PQB);
        const __nv_bfloat16* qh_ = (const __nv_bfloat16*)(smem + OQH + tid * PQB);
        const __nv_bfloat16* ql_ = (const __nv_bfloat16*)(smem + OQL + tid * PQB);
        const float* zf = (const float*)(smem + OZ);
        float s = 0.f;
        for (int j = 0; j < NF; j++)
            s += __bfloat162float(ah_[j]) + __bfloat162float(al_[j]);
        for (int j = 0; j < NF; j++)
            s += (__bfloat162float(qh_[j]) + __bfloat162float(ql_[j])) * zf[j];
        ((float*)(smem + ODEN))[tid] = s;
    }
    __syncthreads();

    float accO[2][4][4];
#pragma unroll
    for (int mt = 0; mt < 2; mt++)
#pragma unroll
        for (int nt = 0; nt < 4; nt++)
#pragma unroll
            for (int i = 0; i < 4; i++) accO[mt][nt][i] = 0.f;

    int bt_row = (lane & 7) + ((lane >> 3) & 1) * 8;
    int bt_nt = lane >> 4;

#pragma unroll
    for (int kt = 0; kt < 16; kt++) {
        int isA = (kt < 8);
        uint32_t abase = isA ? OKH : OQH;
        uint32_t abl = isA ? OKL : OQL;
        uint32_t bbase = isA ? OVH : OSH;
        uint32_t bbl = isA ? OVL : OSL;
        int kk = (kt & 7) * 16;
        uint32_t fah[2][4], fal[2][4];
#pragma unroll
        for (int mt = 0; mt < 2; mt++) {
            uint32_t addr = sm + abase + (wm * 32 + mt * 16 + a_row) * PQB +
                            (kk + a_koff) * 2;
            ldm_x4(fah[mt], addr);
            ldm_x4(fal[mt], addr + (abl - abase));
        }
        uint32_t fbh[4][2], fbl[4][2];
#pragma unroll
        for (int ntp = 0; ntp < 2; ntp++) {
            uint32_t addr = sm + bbase + (kk + bt_row) * PVB +
                            (wn * 32 + ntp * 16 + bt_nt * 8) * 2;
            uint32_t t4[4];
            ldm_x4t(t4, addr);
            fbh[2 * ntp][0] = t4[0]; fbh[2 * ntp][1] = t4[1];
            fbh[2 * ntp + 1][0] = t4[2]; fbh[2 * ntp + 1][1] = t4[3];
            ldm_x4t(t4, addr + (bbl - bbase));
            fbl[2 * ntp][0] = t4[0]; fbl[2 * ntp][1] = t4[1];
            fbl[2 * ntp + 1][0] = t4[2]; fbl[2 * ntp + 1][1] = t4[3];
        }
#pragma unroll
        for (int mt = 0; mt < 2; mt++)
#pragma unroll
            for (int nt = 0; nt < 4; nt++) {
                mma16816(accO[mt][nt], fah[mt], fbh[nt]);
                mma16816(accO[mt][nt], fal[mt], fbh[nt]);
                mma16816(accO[mt][nt], fah[mt], fbl[nt]);
            }
    }

    const float* den = (const float*)(smem + ODEN);
#pragma unroll
    for (int mt = 0; mt < 2; mt++)
#pragma unroll
        for (int nt = 0; nt < 4; nt++)
#pragma unroll
            for (int rh = 0; rh < 2; rh++) {
                int row = wm * 32 + mt * 16 + gid + rh * 8;
                int col = wn * 32 + nt * 8 + tig * 2;
                float inv = 1.0f / (den[row] + EPSV);
                float v0 = accO[mt][nt][2 * rh] * inv;
                float v1 = accO[mt][nt][2 * rh + 1] * inv;
                __nv_bfloat162 lo;
                __nv_bfloat162 hi = split_pair(v0, v1, lo);
                size_t go = (size_t)(b * TT + c * CC + row) * DM + h * HD + col;
                *(__nv_bfloat162*)(yh + go) = hi;
                *(__nv_bfloat162*)(yl + go) = lo;
            }
}

// ---------------- launcher ----------------------------------------------------
extern "C" void kernel_launch(void* const* d_in, const int* in_sizes, int n_in,
                              void* d_out, int out_size) {
    const float* x  = (const float*)d_in[0];
    const float* Wq = (const float*)d_in[1];
    const float* Wk = (const float*)d_in[2];
    const float* Wv = (const float*)d_in[3];
    const float* Wo = (const float*)d_in[4];
    const float* Wf = (const float*)d_in[5];
    float* out = (float*)d_out;

    float *pq, *pk, *pS, *pz;
    __nv_bfloat16 *pxh, *pxl, *pvh, *pvl, *pyh, *pyl, *pwh, *pwl;
    __nv_bfloat16 *pqph, *pqpl, *pkph, *pkpl;
    cudaGetSymbolAddress((void**)&pq,  g_q);
    cudaGetSymbolAddress((void**)&pk,  g_k);
    cudaGetSymbolAddress((void**)&pS,  g_S);
    cudaGetSymbolAddress((void**)&pz,  g_z);
    cudaGetSymbolAddress((void**)&pxh, g_xh);
    cudaGetSymbolAddress((void**)&pxl, g_xl);
    cudaGetSymbolAddress((void**)&pvh, g_vh);
    cudaGetSymbolAddress((void**)&pvl, g_vl);
    cudaGetSymbolAddress((void**)&pyh, g_yh);
    cudaGetSymbolAddress((void**)&pyl, g_yl);
    cudaGetSymbolAddress((void**)&pwh, g_wh);
    cudaGetSymbolAddress((void**)&pwl, g_wl);
    cudaGetSymbolAddress((void**)&pqph, g_qph);
    cudaGetSymbolAddress((void**)&pqpl, g_qpl);
    cudaGetSymbolAddress((void**)&pkph, g_kph);
    cudaGetSymbolAddress((void**)&pkpl, g_kpl);

    cudaFuncSetAttribute(gemm_big<0>, cudaFuncAttributeMaxDynamicSharedMemorySize, BSMEM);
    cudaFuncSetAttribute(gemm_big<1>, cudaFuncAttributeMaxDynamicSharedMemorySize, BSMEM);
    cudaFuncSetAttribute(feature_mma_kernel, cudaFuncAttributeMaxDynamicSharedMemorySize, F2SMEM);
    cudaFuncSetAttribute(chunk_kv_mma, cudaFuncAttributeMaxDynamicSharedMemorySize, CSMEM);
    cudaFuncSetAttribute(attn_mma_kernel, cudaFuncAttributeMaxDynamicSharedMemorySize, ATTN_SMEM);

    // 1. split x
    split_kernel<<<2048, 256>>>(x, pxh, pxl, ROWS * DM / 4);
    // 2. transpose + split all 4 weights in one launch
    wsplit4_kernel<<<dim3(DM / 32, DM / 32, 4), 256>>>(Wq, Wk, Wv, Wo, pwh, pwl);

    // 3. fused QKV projection (N = 3072), full 3-pass
    gemm_big<1><<<dim3(12, ROWS / BGM), 512, BSMEM>>>(pxh, pxl, pwh, pwl,
                                                      pq, pk, pvh, pvl);

    // 4. feature map (q+k fused per block, 2 CTAs/SM) + attention
    feature_mma_kernel<<<BHT / 128, 256, F2SMEM>>>(pq, pk, Wf,
                                                   pqph, pqpl, pkph, pkpl);
    chunk_kv_mma<<<BB * HH * NCH, 256, CSMEM>>>(pkph, pkpl, pvh, pvl, pS, pz);
    prefix_kernel<<<dim3(BB * HH, 4), 256>>>(pS, pz);
    attn_mma_kernel<<<BB * HH * NCH, 256, ATTN_SMEM>>>(pqph, pqpl, pkph, pkpl,
                                                       pvh, pvl, pS, pz, pyh, pyl);

    // 5. output projection (N = 1024)
    gemm_big<0><<<dim3(4, ROWS / BGM), 512, BSMEM>>>(
        pyh, pyl, pwh + 3 * (size_t)DM * DM, pwl + 3 * (size_t)DM * DM,
        out, nullptr, nullptr, nullptr);
}